// round 16
// baseline (speedup 1.0000x reference)
#include <cuda_runtime.h>
#include <cuda_bf16.h>
#include <cstdint>

// LinearQuant: q = clip(floor(x*16 + 0.5), -128, 127) / 16.  HBM-bound stream.
// R16: final granularity probe. VPT=2 x 256-bit .cs ld/st (the mapped BW
// peak) at 128 threads/block -> 25088 CTAs, finest scheduling granularity.
// R14 showed coarser (512t) loses 1.5%; testing the mirrored direction.
// Session ceiling: ~6.23-6.24 TB/s mixed 1R:1W (~78% of 8TB/s spec).

__device__ __forceinline__ float quant1(float x) {
    float q = floorf(fmaf(x, 16.0f, 0.5f));
    q = fminf(fmaxf(q, -128.0f), 127.0f);
    return q * 0.0625f;
}

__device__ __forceinline__ void ld_v8_cs(const float* p, float r[8]) {
    asm volatile(
        "ld.global.cs.v8.f32 {%0,%1,%2,%3,%4,%5,%6,%7}, [%8];"
        : "=f"(r[0]), "=f"(r[1]), "=f"(r[2]), "=f"(r[3]),
          "=f"(r[4]), "=f"(r[5]), "=f"(r[6]), "=f"(r[7])
        : "l"(p));
}

__device__ __forceinline__ void st_v8_cs(float* p, const float r[8]) {
    asm volatile(
        "st.global.cs.v8.f32 [%0], {%1,%2,%3,%4,%5,%6,%7,%8};"
        :: "l"(p),
           "f"(r[0]), "f"(r[1]), "f"(r[2]), "f"(r[3]),
           "f"(r[4]), "f"(r[5]), "f"(r[6]), "f"(r[7])
        : "memory");
}

#define VPT 2       // 32B chunks per thread (64B/thread total)
#define THREADS 128

__global__ void __launch_bounds__(THREADS) linquant_v8x2_t128_kernel(
    const float* __restrict__ in, float* __restrict__ out, int n8)
{
    // index in units of 8 floats (32B)
    int base = blockIdx.x * (THREADS * VPT) + threadIdx.x;

    if (base + THREADS < n8) {
        float v0[8], v1[8];
        ld_v8_cs(in + (size_t)(base + 0 * THREADS) * 8, v0);
        ld_v8_cs(in + (size_t)(base + 1 * THREADS) * 8, v1);
        #pragma unroll
        for (int j = 0; j < 8; j++) v0[j] = quant1(v0[j]);
        #pragma unroll
        for (int j = 0; j < 8; j++) v1[j] = quant1(v1[j]);
        st_v8_cs(out + (size_t)(base + 0 * THREADS) * 8, v0);
        st_v8_cs(out + (size_t)(base + 1 * THREADS) * 8, v1);
    } else {
        #pragma unroll
        for (int k = 0; k < VPT; k++) {
            int i8 = base + k * THREADS;
            if (i8 < n8) {
                float v[8];
                ld_v8_cs(in + (size_t)i8 * 8, v);
                #pragma unroll
                for (int j = 0; j < 8; j++) v[j] = quant1(v[j]);
                st_v8_cs(out + (size_t)i8 * 8, v);
            }
        }
    }
}

__global__ void __launch_bounds__(256) linquant_tail_kernel(
    const float* __restrict__ in, float* __restrict__ out, int start, int n)
{
    int i = start + blockIdx.x * blockDim.x + threadIdx.x;
    if (i < n) {
        out[i] = quant1(in[i]);
    }
}

extern "C" void kernel_launch(void* const* d_in, const int* in_sizes, int n_in,
                              void* d_out, int out_size) {
    const float* in = (const float*)d_in[0];
    float* out = (float*)d_out;
    int n = in_sizes[0];

    int n8 = n / 8;
    if (n8 > 0) {
        const int per_block = THREADS * VPT;  // in 8-float units
        int blocks = (n8 + per_block - 1) / per_block;
        linquant_v8x2_t128_kernel<<<blocks, THREADS>>>(in, out, n8);
    }
    int rem = n - n8 * 8;
    if (rem > 0) {
        linquant_tail_kernel<<<1, 256>>>(in, out, n8 * 8, n);
    }
}

// round 17
// speedup vs baseline: 1.0005x; 1.0005x over previous
#include <cuda_runtime.h>
#include <cuda_bf16.h>
#include <cstdint>

// LinearQuant: q = clip(floor(x*16 + 0.5), -128, 127) / 16.  HBM-bound stream.
// FINAL (converged, R1-R16): VPT=2 x 256-bit .cs streaming ld/st,
// 256 threads/block, block-interleaved addressing.
// Best measured: 6244 GB/s, 57.25us kernel, 65.568us dur, rel_err 0.0.
//
// Design-space map (all measured):
//   VPT=2/256t: 6244  | VPT=2/128t: 6223 | VPT=1: 6213 | 128-bit VPT=4: 6156
//   VPT=4: 6135-6157  | VPT=2/512t: 6134 | VPT=8: 6111 | chunked: 5688 GB/s
// L2 evict_last/evict_first hints inert cross-launch (two null experiments).
// ~78% of 8TB/s spec is this part's mixed 1R:1W DRAM ceiling (r/w bus
// turnaround); compute pipes all <11% -> nothing further addressable SM-side.

__device__ __forceinline__ float quant1(float x) {
    float q = floorf(fmaf(x, 16.0f, 0.5f));
    q = fminf(fmaxf(q, -128.0f), 127.0f);
    return q * 0.0625f;
}

__device__ __forceinline__ void ld_v8_cs(const float* p, float r[8]) {
    asm volatile(
        "ld.global.cs.v8.f32 {%0,%1,%2,%3,%4,%5,%6,%7}, [%8];"
        : "=f"(r[0]), "=f"(r[1]), "=f"(r[2]), "=f"(r[3]),
          "=f"(r[4]), "=f"(r[5]), "=f"(r[6]), "=f"(r[7])
        : "l"(p));
}

__device__ __forceinline__ void st_v8_cs(float* p, const float r[8]) {
    asm volatile(
        "st.global.cs.v8.f32 [%0], {%1,%2,%3,%4,%5,%6,%7,%8};"
        :: "l"(p),
           "f"(r[0]), "f"(r[1]), "f"(r[2]), "f"(r[3]),
           "f"(r[4]), "f"(r[5]), "f"(r[6]), "f"(r[7])
        : "memory");
}

#define VPT 2  // 32B chunks per thread (64B/thread total)

__global__ void __launch_bounds__(256) linquant_v8x2_kernel(
    const float* __restrict__ in, float* __restrict__ out, int n8)
{
    // index in units of 8 floats (32B)
    int base = blockIdx.x * (blockDim.x * VPT) + threadIdx.x;

    if (base + blockDim.x < n8) {
        float v0[8], v1[8];
        ld_v8_cs(in + (size_t)(base + 0 * blockDim.x) * 8, v0);
        ld_v8_cs(in + (size_t)(base + 1 * blockDim.x) * 8, v1);
        #pragma unroll
        for (int j = 0; j < 8; j++) v0[j] = quant1(v0[j]);
        #pragma unroll
        for (int j = 0; j < 8; j++) v1[j] = quant1(v1[j]);
        st_v8_cs(out + (size_t)(base + 0 * blockDim.x) * 8, v0);
        st_v8_cs(out + (size_t)(base + 1 * blockDim.x) * 8, v1);
    } else {
        #pragma unroll
        for (int k = 0; k < VPT; k++) {
            int i8 = base + k * blockDim.x;
            if (i8 < n8) {
                float v[8];
                ld_v8_cs(in + (size_t)i8 * 8, v);
                #pragma unroll
                for (int j = 0; j < 8; j++) v[j] = quant1(v[j]);
                st_v8_cs(out + (size_t)i8 * 8, v);
            }
        }
    }
}

__global__ void __launch_bounds__(256) linquant_tail_kernel(
    const float* __restrict__ in, float* __restrict__ out, int start, int n)
{
    int i = start + blockIdx.x * blockDim.x + threadIdx.x;
    if (i < n) {
        out[i] = quant1(in[i]);
    }
}

extern "C" void kernel_launch(void* const* d_in, const int* in_sizes, int n_in,
                              void* d_out, int out_size) {
    const float* in = (const float*)d_in[0];
    float* out = (float*)d_out;
    int n = in_sizes[0];

    int n8 = n / 8;
    if (n8 > 0) {
        const int threads = 256;
        const int per_block = threads * VPT;  // in 8-float units
        int blocks = (n8 + per_block - 1) / per_block;
        linquant_v8x2_kernel<<<blocks, threads>>>(in, out, n8);
    }
    int rem = n - n8 * 8;
    if (rem > 0) {
        linquant_tail_kernel<<<1, 256>>>(in, out, n8 * 8, n);
    }
}